// round 5
// baseline (speedup 1.0000x reference)
#include <cuda_runtime.h>
#include <math.h>

// Problem constants: B=16, C=512, H=W=64, G=16, CPG=32, HID=8
#define BN   16
#define CN   512
#define GN   16
#define CPGN 32
#define HIDN 8
#define HWN  4096   // 64*64
#define NIMG (BN * CN)

__device__ float g_pooled[NIMG];
__device__ float g_scale[NIMG];

// ---------------------------------------------------------------------------
// Kernel 1: spatial mean per (b, c). TWO images per block -> 8 independent
// float4 loads batched per thread (MLP 8). Ascending order leaves the x tail
// resident in L2 for the scale kernel.
// ---------------------------------------------------------------------------
__global__ void pool_kernel(const float* __restrict__ x) {
    const int img0 = blockIdx.x * 2;       // 0,2,..,8190
    const float4* p0 = reinterpret_cast<const float4*>(x + (size_t)img0 * HWN);
    const float4* p1 = p0 + (HWN / 4);

    float4 v[8];
#pragma unroll
    for (int i = 0; i < 4; i++) v[i]     = p0[threadIdx.x + i * 256];
#pragma unroll
    for (int i = 0; i < 4; i++) v[4 + i] = p1[threadIdx.x + i * 256];

    float s0 = 0.f, s1 = 0.f;
#pragma unroll
    for (int i = 0; i < 4; i++) s0 += (v[i].x + v[i].y) + (v[i].z + v[i].w);
#pragma unroll
    for (int i = 4; i < 8; i++) s1 += (v[i].x + v[i].y) + (v[i].z + v[i].w);

#pragma unroll
    for (int o = 16; o; o >>= 1) {
        s0 += __shfl_down_sync(0xffffffffu, s0, o);
        s1 += __shfl_down_sync(0xffffffffu, s1, o);
    }
    __shared__ float ws0[8], ws1[8];
    if ((threadIdx.x & 31) == 0) {
        ws0[threadIdx.x >> 5] = s0;
        ws1[threadIdx.x >> 5] = s1;
    }
    __syncthreads();
    if (threadIdx.x < 2) {
        float* ws = threadIdx.x ? ws1 : ws0;
        float t = 0.f;
#pragma unroll
        for (int i = 0; i < 8; i++) t += ws[i];
        g_pooled[img0 + threadIdx.x] = t * (1.0f / HWN);
    }
}

// ---------------------------------------------------------------------------
// Kernel 2: all gating math. One block per batch, 512 threads = 512 channels.
// ---------------------------------------------------------------------------
__device__ __forceinline__ float sigmoidf_(float v) {
    return 1.0f / (1.0f + expf(-v));
}

__global__ void gate_kernel(const float* __restrict__ gw1, const float* __restrict__ gb1,
                            const float* __restrict__ gw2, const float* __restrict__ gb2,
                            const float* __restrict__ cw1, const float* __restrict__ cb1,
                            const float* __restrict__ cw2, const float* __restrict__ cb2) {
    const int b = blockIdx.x;
    const int tid = threadIdx.x;          // 0..511
    const int g = tid >> 5, c = tid & 31;

    __shared__ float pooled1[CN], gate1[CN], pooled2[CN], gate2[CN];
    __shared__ float h[GN][HIDN];
    __shared__ float glob[GN], wv[GN], hc[HIDN];

    pooled1[tid] = g_pooled[b * CN + tid];
    __syncthreads();

    // SE pass 1 (original channel order)
    if (c < HIDN) {
        float s = gb1[c];
#pragma unroll
        for (int j = 0; j < CPGN; j++) s += pooled1[g * CPGN + j] * gw1[c * CPGN + j];
        h[g][c] = fmaxf(s, 0.f);
    }
    __syncthreads();
    {
        float s = gb2[c];
#pragma unroll
        for (int o = 0; o < HIDN; o++) s += h[g][o] * gw2[c * HIDN + o];
        gate1[tid] = sigmoidf_(s);
    }
    __syncthreads();

    // channel shuffle on pooled values: ch2 -> ch_orig
    {
        const int g1 = tid & 15, cpg1 = tid >> 4;
        const int och = g1 * CPGN + cpg1;
        pooled2[tid] = pooled1[och] * gate1[och];
    }
    __syncthreads();

    // SE pass 2 (shuffled order)
    if (c < HIDN) {
        float s = gb1[c];
#pragma unroll
        for (int j = 0; j < CPGN; j++) s += pooled2[g * CPGN + j] * gw1[c * CPGN + j];
        h[g][c] = fmaxf(s, 0.f);
    }
    __syncthreads();
    {
        float s = gb2[c];
#pragma unroll
        for (int o = 0; o < HIDN; o++) s += h[g][o] * gw2[c * HIDN + o];
        gate2[tid] = sigmoidf_(s);
    }
    __syncthreads();

    // cross-group gate
    if (tid < GN) {
        float s = 0.f;
#pragma unroll
        for (int j = 0; j < CPGN; j++) s += pooled2[tid * CPGN + j] * gate2[tid * CPGN + j];
        glob[tid] = s * (1.0f / CPGN);
    }
    __syncthreads();
    if (tid < HIDN) {
        float s = cb1[tid];
#pragma unroll
        for (int j = 0; j < GN; j++) s += glob[j] * cw1[tid * GN + j];
        hc[tid] = fmaxf(s, 0.f);
    }
    __syncthreads();
    if (tid < GN) {
        float s = cb2[tid];
#pragma unroll
        for (int o = 0; o < HIDN; o++) s += hc[o] * cw2[tid * HIDN + o];
        wv[tid] = sigmoidf_(s);
    }
    __syncthreads();

    // compose final per-channel scale, indexed by output channel
    {
        const int g2 = tid >> 5, c2 = tid & 31;  // tid == ch2
        const int g1 = tid & 15, cpg1 = tid >> 4;
        const int och = g1 * CPGN + cpg1;
        const float s = gate1[och] * gate2[tid] * wv[g2];
        const int ch_out = c2 * GN + g2;
        g_scale[b * CN + ch_out] = s;
    }
}

// ---------------------------------------------------------------------------
// Kernel 3: out[b, ch_out] = x[b, ch_orig] * scale[b, ch_out].
// TWO images per block, 8 loads front-batched before any store. Reversed
// image order consumes the L2-resident x tail first; __stcs output stores
// (evict-first) protect x lines from write-stream eviction.
// ---------------------------------------------------------------------------
__device__ __forceinline__ int src_channel(int ch_out) {
    const int c2 = ch_out >> 4, g2 = ch_out & 15;
    const int ch2 = g2 * CPGN + c2;
    const int g1 = ch2 & 15, cpg1 = ch2 >> 4;
    return g1 * CPGN + cpg1;
}

__global__ void scale_kernel(const float* __restrict__ x, float* __restrict__ out) {
    const int bc0 = NIMG - 1 - blockIdx.x * 2;   // descending pairs
    const int bc1 = bc0 - 1;

    const int b0 = bc0 >> 9, ch0 = bc0 & 511;
    const int b1 = bc1 >> 9, ch1 = bc1 & 511;
    const int och0 = src_channel(ch0);
    const int och1 = src_channel(ch1);

    const float s0 = g_scale[bc0];
    const float s1 = g_scale[bc1];

    const float4* pin0 = reinterpret_cast<const float4*>(x + ((size_t)b0 * CN + och0) * HWN);
    const float4* pin1 = reinterpret_cast<const float4*>(x + ((size_t)b1 * CN + och1) * HWN);
    float4* pout0 = reinterpret_cast<float4*>(out + (size_t)bc0 * HWN);
    float4* pout1 = reinterpret_cast<float4*>(out + (size_t)bc1 * HWN);

    float4 v[8];
#pragma unroll
    for (int i = 0; i < 4; i++) v[i]     = pin0[threadIdx.x + i * 256];
#pragma unroll
    for (int i = 0; i < 4; i++) v[4 + i] = pin1[threadIdx.x + i * 256];

#pragma unroll
    for (int i = 0; i < 4; i++) {
        v[i].x *= s0; v[i].y *= s0; v[i].z *= s0; v[i].w *= s0;
        __stcs(&pout0[threadIdx.x + i * 256], v[i]);
    }
#pragma unroll
    for (int i = 0; i < 4; i++) {
        v[4+i].x *= s1; v[4+i].y *= s1; v[4+i].z *= s1; v[4+i].w *= s1;
        __stcs(&pout1[threadIdx.x + i * 256], v[4 + i]);
    }
}

extern "C" void kernel_launch(void* const* d_in, const int* in_sizes, int n_in,
                              void* d_out, int out_size) {
    const float* x   = (const float*)d_in[0];
    const float* gw1 = (const float*)d_in[1];
    const float* gb1 = (const float*)d_in[2];
    const float* gw2 = (const float*)d_in[3];
    const float* gb2 = (const float*)d_in[4];
    const float* cw1 = (const float*)d_in[5];
    const float* cb1 = (const float*)d_in[6];
    const float* cw2 = (const float*)d_in[7];
    const float* cb2 = (const float*)d_in[8];
    float* out = (float*)d_out;

    pool_kernel<<<NIMG / 2, 256>>>(x);
    gate_kernel<<<BN, CN>>>(gw1, gb1, gw2, gb2, cw1, cb1, cw2, cb2);
    scale_kernel<<<NIMG / 2, 256>>>(x, out);
}